// round 6
// baseline (speedup 1.0000x reference)
#include <cuda_runtime.h>
#include <stdint.h>

// BottleNeck binary block, GB300.
// B=8, C=128, Ci=32, H=128, W=256.
// bin_conv == popcount dot on sign bits; BN+PReLU before conv2/conv3 reduce to
// per-channel integer thresholds (inv>0, a>0 preserve sign). Only conv3's
// output needs floats (bn3 + prelu3 + residual + prelu_out).

#define EPSC 1e-5f
#define Bn  8
#define Cc  128
#define CI  32
#define Hh  128
#define Ww  256
#define HW  32768           // Hh*Ww
#define CHW (Cc*HW)         // 4194304
#define BHW (Bn*HW)         // 262144

// ---- device scratch (no allocations allowed) ----
__device__ __align__(16) uint32_t g_h1b[BHW];   // conv1 output sign bits (32 oc / pixel)
__device__ __align__(16) uint32_t g_h2b[BHW];   // conv2 output sign bits
__device__ uint32_t g_wb1[CI][4];   // w1 sign bits: 128 in-ch -> 4 words
__device__ uint32_t g_wb2[CI][9];   // w2 sign bits: per (oc, tap) 32 in-ch
__device__ uint32_t g_wb3[Cc];      // w3 sign bits: 32 in-ch
__device__ float g_t1p[CI];         // conv1: bit = (popc < t1p)
__device__ float g_t2p[CI];         // conv2 fast (all 9 taps valid): bit = (popc < t2p)
__device__ float g_t2raw[CI];       // conv2 slow: bit = (dot > t2raw)
__device__ float g_fa3[Cc];         // -2*inv3
__device__ float g_fb3[Cc];         // 32*inv3 + beta3

// ---------------------------------------------------------------------------
// K0: pack weights, compute thresholds. One block, 512 threads (480 active).
// ---------------------------------------------------------------------------
__global__ void k_prep(const float* __restrict__ w1,
                       const float* __restrict__ g1, const float* __restrict__ b1,
                       const float* __restrict__ m1, const float* __restrict__ v1,
                       const float* __restrict__ w2,
                       const float* __restrict__ g2, const float* __restrict__ b2,
                       const float* __restrict__ m2, const float* __restrict__ v2,
                       const float* __restrict__ w3,
                       const float* __restrict__ g3, const float* __restrict__ b3,
                       const float* __restrict__ m3, const float* __restrict__ v3)
{
    int t = threadIdx.x;
    if (t < CI) {
        // w1: [32,128,1,1]
        uint32_t acc[4] = {0u, 0u, 0u, 0u};
        #pragma unroll 4
        for (int c = 0; c < Cc; ++c)
            if (w1[t * Cc + c] > 0.f) acc[c >> 5] |= 1u << (c & 31);
        g_wb1[t][0] = acc[0]; g_wb1[t][1] = acc[1];
        g_wb1[t][2] = acc[2]; g_wb1[t][3] = acc[3];
        float inv  = g1[t] * rsqrtf(v1[t] + EPSC);
        float beta = b1[t] - m1[t] * inv;
        // bit = (128 - 2p)*inv + beta > 0  <=>  p < (128 + beta/inv)/2
        g_t1p[t] = 0.5f * (128.f + beta / inv);
    } else if (t < 2 * CI) {
        int oc = t - CI;
        float inv  = g2[oc] * rsqrtf(v2[oc] + EPSC);
        float beta = b2[oc] - m2[oc] * inv;
        float traw = -beta / inv;            // bit = (dot > traw)
        g_t2raw[oc] = traw;
        g_t2p[oc]   = 0.5f * (288.f - traw); // dot = 288 - 2P (interior)
    } else if (t >= 64 && t < 64 + CI * 9) {
        int idx = t - 64;
        int oc = idx / 9, tap = idx % 9;
        // w2: [32,32,3,3] -> (oc*32+ic)*9 + tap
        uint32_t acc = 0u;
        #pragma unroll
        for (int ic = 0; ic < CI; ++ic)
            if (w2[(oc * CI + ic) * 9 + tap] > 0.f) acc |= 1u << ic;
        g_wb2[oc][tap] = acc;
    } else if (t >= 352 && t < 352 + Cc) {
        int oc = t - 352;
        uint32_t acc = 0u;
        #pragma unroll
        for (int ic = 0; ic < CI; ++ic)
            if (w3[oc * CI + ic] > 0.f) acc |= 1u << ic;
        g_wb3[oc] = acc;
        float inv  = g3[oc] * rsqrtf(v3[oc] + EPSC);
        float beta = b3[oc] - m3[oc] * inv;
        g_fa3[oc] = -2.f * inv;
        g_fb3[oc] = 32.f * inv + beta;  // y=32-2p: f = p*fa + fb
    }
}

// ---------------------------------------------------------------------------
// K1: conv1 (1x1, 128->32) fused binarize+pack+dot+threshold.
// One thread = 4 consecutive pixels (same row, float4-coalesced channel reads).
// 65536 threads.
// ---------------------------------------------------------------------------
__global__ void __launch_bounds__(256) k_conv1(const float* __restrict__ x)
{
    int t = blockIdx.x * 256 + threadIdx.x;
    int pix4 = t << 2;
    int b  = pix4 >> 15;
    int hw = pix4 & (HW - 1);
    const float4* xp = reinterpret_cast<const float4*>(x)
                       + ((size_t)b * (CHW / 4) + (hw >> 2));

    uint32_t bits[4][4];  // [word][pixel]
    #pragma unroll
    for (int wi = 0; wi < 4; ++wi)
        #pragma unroll
        for (int j = 0; j < 4; ++j) bits[wi][j] = 0u;

    #pragma unroll
    for (int c = 0; c < Cc; ++c) {
        float4 v = __ldg(xp + c * (HW / 4));
        const int wi = c >> 5;
        const uint32_t m = 1u << (c & 31);
        if (v.x > 0.f) bits[wi][0] |= m;
        if (v.y > 0.f) bits[wi][1] |= m;
        if (v.z > 0.f) bits[wi][2] |= m;
        if (v.w > 0.f) bits[wi][3] |= m;
    }

    uint32_t r[4] = {0u, 0u, 0u, 0u};
    #pragma unroll 4
    for (int oc = 0; oc < CI; ++oc) {
        uint32_t w0 = g_wb1[oc][0], w1 = g_wb1[oc][1];
        uint32_t w2 = g_wb1[oc][2], w3 = g_wb1[oc][3];
        float th = g_t1p[oc];
        #pragma unroll
        for (int j = 0; j < 4; ++j) {
            int p = __popc(bits[0][j] ^ w0) + __popc(bits[1][j] ^ w1)
                  + __popc(bits[2][j] ^ w2) + __popc(bits[3][j] ^ w3);
            if ((float)p < th) r[j] |= 1u << oc;
        }
    }
    *reinterpret_cast<uint4*>(&g_h1b[pix4]) = make_uint4(r[0], r[1], r[2], r[3]);
}

// ---------------------------------------------------------------------------
// K2: conv2 (3x3 pad 1, 32->32) on bitplanes. One thread = 4 pixels.
// padding pads the *binarized* tensor with zeros -> border taps contribute 0.
// Fast path: all 9 taps valid (95.4% of threads). Slow path: exact per-tap.
// 65536 threads.
// ---------------------------------------------------------------------------
__global__ void __launch_bounds__(256) k_conv2()
{
    int t = blockIdx.x * 256 + threadIdx.x;
    int pix4 = t << 2;
    int b  = pix4 >> 15;
    int hw = pix4 & (HW - 1);
    int h  = hw >> 8;          // Ww = 256
    int w0 = hw & (Ww - 1);
    const uint32_t* hb = g_h1b + b * HW;
    uint32_t r[4] = {0u, 0u, 0u, 0u};

    bool fast = (h > 0) & (h < Hh - 1) & (w0 > 0) & (w0 + 4 < Ww);
    if (fast) {
        uint32_t n0[6], n1[6], n2[6];
        {
            int base = (h - 1) * Ww + w0;
            uint4 m = *reinterpret_cast<const uint4*>(hb + base);
            n0[0] = hb[base - 1]; n0[1] = m.x; n0[2] = m.y; n0[3] = m.z; n0[4] = m.w; n0[5] = hb[base + 4];
            base += Ww;
            m = *reinterpret_cast<const uint4*>(hb + base);
            n1[0] = hb[base - 1]; n1[1] = m.x; n1[2] = m.y; n1[3] = m.z; n1[4] = m.w; n1[5] = hb[base + 4];
            base += Ww;
            m = *reinterpret_cast<const uint4*>(hb + base);
            n2[0] = hb[base - 1]; n2[1] = m.x; n2[2] = m.y; n2[3] = m.z; n2[4] = m.w; n2[5] = hb[base + 4];
        }
        #pragma unroll 2
        for (int oc = 0; oc < CI; ++oc) {
            uint32_t wt0 = g_wb2[oc][0], wt1 = g_wb2[oc][1], wt2 = g_wb2[oc][2];
            uint32_t wt3 = g_wb2[oc][3], wt4 = g_wb2[oc][4], wt5 = g_wb2[oc][5];
            uint32_t wt6 = g_wb2[oc][6], wt7 = g_wb2[oc][7], wt8 = g_wb2[oc][8];
            float th = g_t2p[oc];
            #pragma unroll
            for (int j = 0; j < 4; ++j) {
                int P = __popc(n0[j] ^ wt0) + __popc(n0[j+1] ^ wt1) + __popc(n0[j+2] ^ wt2)
                      + __popc(n1[j] ^ wt3) + __popc(n1[j+1] ^ wt4) + __popc(n1[j+2] ^ wt5)
                      + __popc(n2[j] ^ wt6) + __popc(n2[j+1] ^ wt7) + __popc(n2[j+2] ^ wt8);
                if ((float)P < th) r[j] |= 1u << oc;
            }
        }
    } else {
        #pragma unroll
        for (int j = 0; j < 4; ++j) {
            int wj = w0 + j;
            uint32_t rb = 0u;
            for (int oc = 0; oc < CI; ++oc) {
                int acc = 0;
                for (int kh = 0; kh < 3; ++kh) {
                    int rr = h - 1 + kh;
                    if (rr < 0 || rr >= Hh) continue;
                    for (int kw = 0; kw < 3; ++kw) {
                        int cc = wj - 1 + kw;
                        if (cc < 0 || cc >= Ww) continue;
                        acc += 32 - 2 * __popc(hb[rr * Ww + cc] ^ g_wb2[oc][kh * 3 + kw]);
                    }
                }
                if ((float)acc > g_t2raw[oc]) rb |= 1u << oc;
            }
            r[j] = rb;
        }
    }
    *reinterpret_cast<uint4*>(&g_h2b[pix4]) = make_uint4(r[0], r[1], r[2], r[3]);
}

// ---------------------------------------------------------------------------
// K3: conv3 (1x1, 32->128) + bn3 + prelu3 + residual + prelu_out.
// One thread = 4 consecutive outputs (float4 in/out). 8388608 threads.
// ---------------------------------------------------------------------------
__global__ void __launch_bounds__(256) k_conv3(const float* __restrict__ x,
                                               float* __restrict__ out,
                                               const float* __restrict__ a3p,
                                               const float* __restrict__ aoutp)
{
    int t = blockIdx.x * 256 + threadIdx.x;     // 0 .. 8388607
    int b   = t >> 20;                           // i4 / CHW
    int oc  = (t >> 13) & (Cc - 1);              // (i4 % CHW) / HW
    int hw4 = t & 8191;                          // (i4 % HW) / 4

    float a3   = __ldg(a3p);
    float aout = __ldg(aoutp);
    float fa = g_fa3[oc], fb = g_fb3[oc];
    uint32_t wv = g_wb3[oc];

    uint4 hq = *reinterpret_cast<const uint4*>(&g_h2b[(b << 15) + (hw4 << 2)]);
    size_t i4 = (size_t)t << 2;
    float4 xv = *reinterpret_cast<const float4*>(x + i4);
    float4 o;

    {
        float f = fmaf((float)__popc(hq.x ^ wv), fa, fb);
        f = fmaxf(f, 0.f) + a3 * fminf(f, 0.f);
        float s = f + xv.x;
        o.x = fmaxf(s, 0.f) + aout * fminf(s, 0.f);
    }
    {
        float f = fmaf((float)__popc(hq.y ^ wv), fa, fb);
        f = fmaxf(f, 0.f) + a3 * fminf(f, 0.f);
        float s = f + xv.y;
        o.y = fmaxf(s, 0.f) + aout * fminf(s, 0.f);
    }
    {
        float f = fmaf((float)__popc(hq.z ^ wv), fa, fb);
        f = fmaxf(f, 0.f) + a3 * fminf(f, 0.f);
        float s = f + xv.z;
        o.z = fmaxf(s, 0.f) + aout * fminf(s, 0.f);
    }
    {
        float f = fmaf((float)__popc(hq.w ^ wv), fa, fb);
        f = fmaxf(f, 0.f) + a3 * fminf(f, 0.f);
        float s = f + xv.w;
        o.w = fmaxf(s, 0.f) + aout * fminf(s, 0.f);
    }
    *reinterpret_cast<float4*>(out + i4) = o;
}

// ---------------------------------------------------------------------------
extern "C" void kernel_launch(void* const* d_in, const int* in_sizes, int n_in,
                              void* d_out, int out_size)
{
    (void)in_sizes; (void)n_in; (void)out_size;
    const float* x  = (const float*)d_in[0];
    const float* w1 = (const float*)d_in[1];
    const float* g1 = (const float*)d_in[2];
    const float* b1 = (const float*)d_in[3];
    const float* m1 = (const float*)d_in[4];
    const float* v1 = (const float*)d_in[5];
    /* a1 = d_in[6] (unused: sign-preserving) */
    const float* w2 = (const float*)d_in[7];
    const float* g2 = (const float*)d_in[8];
    const float* b2 = (const float*)d_in[9];
    const float* m2 = (const float*)d_in[10];
    const float* v2 = (const float*)d_in[11];
    /* a2 = d_in[12] (unused) */
    const float* w3 = (const float*)d_in[13];
    const float* g3 = (const float*)d_in[14];
    const float* b3 = (const float*)d_in[15];
    const float* m3 = (const float*)d_in[16];
    const float* v3 = (const float*)d_in[17];
    const float* a3   = (const float*)d_in[18];
    const float* aout = (const float*)d_in[19];

    k_prep<<<1, 512>>>(w1, g1, b1, m1, v1,
                       w2, g2, b2, m2, v2,
                       w3, g3, b3, m3, v3);
    k_conv1<<<256, 256>>>(x);
    k_conv2<<<256, 256>>>();
    k_conv3<<<32768, 256>>>(x, (float*)d_out, a3, aout);
}

// round 8
// speedup vs baseline: 1.1151x; 1.1151x over previous
#include <cuda_runtime.h>
#include <stdint.h>

// BottleNeck binary block, GB300.
// B=8, C=128, Ci=32, H=128, W=256.
// bin_conv == popcount dot on sign bits; BN+PReLU before conv2/conv3 reduce to
// per-channel INTEGER thresholds (inv>0, a>0 preserve sign; p<t <=> p<ceil(t)
// for integer p). Only conv3's output needs floats.

#define EPSC 1e-5f
#define Bn  8
#define Cc  128
#define CI  32
#define Hh  128
#define Ww  256
#define HW  32768           // Hh*Ww
#define CHW (Cc*HW)         // 4194304
#define BHW (Bn*HW)         // 262144

// ---- device scratch (no allocations allowed) ----
__device__ __align__(16) uint32_t g_h1b[BHW];   // conv1 output sign bits
__device__ __align__(16) uint32_t g_h2b[BHW];   // conv2 output sign bits
__device__ uint32_t g_wb1[CI][4];   // w1 sign bits: 128 in-ch -> 4 words
__device__ uint32_t g_wb2[CI][9];   // w2 sign bits: per (oc, tap) 32 in-ch
__device__ uint32_t g_wb3[Cc];      // w3 sign bits: 32 in-ch
__device__ int g_t1i[CI];           // conv1: bit = (popc < t1i)        [= ceil(t1p)]
__device__ int g_t2pi[CI];          // conv2 fast: bit = (popc < t2pi)  [= ceil(t2p)]
__device__ int g_t2ri[CI];          // conv2 slow: bit = (dot > t2ri)   [= floor(traw)]
__device__ float g_fa3[Cc];         // -2*inv3
__device__ float g_fb3[Cc];         // 32*inv3 + beta3

// ---------------------------------------------------------------------------
// K0: pack weights, compute thresholds. One block, 512 threads (480 active).
// ---------------------------------------------------------------------------
__global__ void k_prep(const float* __restrict__ w1,
                       const float* __restrict__ g1, const float* __restrict__ b1,
                       const float* __restrict__ m1, const float* __restrict__ v1,
                       const float* __restrict__ w2,
                       const float* __restrict__ g2, const float* __restrict__ b2,
                       const float* __restrict__ m2, const float* __restrict__ v2,
                       const float* __restrict__ w3,
                       const float* __restrict__ g3, const float* __restrict__ b3,
                       const float* __restrict__ m3, const float* __restrict__ v3)
{
    int t = threadIdx.x;
    if (t < CI) {
        // w1: [32,128,1,1]
        uint32_t acc[4] = {0u, 0u, 0u, 0u};
        #pragma unroll 4
        for (int c = 0; c < Cc; ++c)
            if (w1[t * Cc + c] > 0.f) acc[c >> 5] |= 1u << (c & 31);
        g_wb1[t][0] = acc[0]; g_wb1[t][1] = acc[1];
        g_wb1[t][2] = acc[2]; g_wb1[t][3] = acc[3];
        float inv  = g1[t] * rsqrtf(v1[t] + EPSC);
        float beta = b1[t] - m1[t] * inv;
        // bit = (128 - 2p)*inv + beta > 0  <=>  p < (128 + beta/inv)/2
        g_t1i[t] = (int)ceilf(0.5f * (128.f + beta / inv));
    } else if (t < 2 * CI) {
        int oc = t - CI;
        float inv  = g2[oc] * rsqrtf(v2[oc] + EPSC);
        float beta = b2[oc] - m2[oc] * inv;
        float traw = -beta / inv;                       // bit = (dot > traw)
        g_t2ri[oc] = (int)floorf(traw);                 // dot > floor(traw)
        g_t2pi[oc] = (int)ceilf(0.5f * (288.f - traw)); // interior: dot = 288-2P
    } else if (t >= 64 && t < 64 + CI * 9) {
        int idx = t - 64;
        int oc = idx / 9, tap = idx % 9;
        // w2: [32,32,3,3] -> (oc*32+ic)*9 + tap
        uint32_t acc = 0u;
        #pragma unroll
        for (int ic = 0; ic < CI; ++ic)
            if (w2[(oc * CI + ic) * 9 + tap] > 0.f) acc |= 1u << ic;
        g_wb2[oc][tap] = acc;
    } else if (t >= 352 && t < 352 + Cc) {
        int oc = t - 352;
        uint32_t acc = 0u;
        #pragma unroll
        for (int ic = 0; ic < CI; ++ic)
            if (w3[oc * CI + ic] > 0.f) acc |= 1u << ic;
        g_wb3[oc] = acc;
        float inv  = g3[oc] * rsqrtf(v3[oc] + EPSC);
        float beta = b3[oc] - m3[oc] * inv;
        g_fa3[oc] = -2.f * inv;
        g_fb3[oc] = 32.f * inv + beta;  // y=32-2p: f = p*fa + fb
    }
}

// ---------------------------------------------------------------------------
// K1: conv1 (1x1, 128->32) fused binarize+pack+dot+threshold.
// One thread = 2 consecutive pixels (float2-coalesced channel reads).
// 131072 threads. Weights + thresholds staged in smem.
// ---------------------------------------------------------------------------
__global__ void __launch_bounds__(256) k_conv1(const float* __restrict__ x)
{
    __shared__ uint32_t swb[CI][4];
    __shared__ int sth[CI];
    int tid = threadIdx.x;
    if (tid < 128) ((uint32_t*)swb)[tid] = ((const uint32_t*)g_wb1)[tid];
    else if (tid < 128 + CI) sth[tid - 128] = g_t1i[tid - 128];
    __syncthreads();

    int t = blockIdx.x * 256 + tid;
    int pix2 = t << 1;
    int b  = pix2 >> 15;
    int hw = pix2 & (HW - 1);
    const float2* xp = reinterpret_cast<const float2*>(x)
                       + ((size_t)b * (CHW / 2) + (hw >> 1));

    uint32_t bits[4][2];
    #pragma unroll
    for (int wi = 0; wi < 4; ++wi) { bits[wi][0] = 0u; bits[wi][1] = 0u; }

    #pragma unroll
    for (int c = 0; c < Cc; ++c) {
        float2 v = __ldg(xp + c * (HW / 2));
        const int wi = c >> 5;
        const uint32_t m = 1u << (c & 31);
        if (v.x > 0.f) bits[wi][0] |= m;
        if (v.y > 0.f) bits[wi][1] |= m;
    }

    uint32_t r0 = 0u, r1 = 0u;
    #pragma unroll 8
    for (int oc = 0; oc < CI; ++oc) {
        uint32_t w0 = swb[oc][0], w1 = swb[oc][1];
        uint32_t w2 = swb[oc][2], w3 = swb[oc][3];
        int th = sth[oc];
        int p0 = __popc(bits[0][0] ^ w0) + __popc(bits[1][0] ^ w1)
               + __popc(bits[2][0] ^ w2) + __popc(bits[3][0] ^ w3);
        int p1 = __popc(bits[0][1] ^ w0) + __popc(bits[1][1] ^ w1)
               + __popc(bits[2][1] ^ w2) + __popc(bits[3][1] ^ w3);
        if (p0 < th) r0 |= 1u << oc;
        if (p1 < th) r1 |= 1u << oc;
    }
    *reinterpret_cast<uint2*>(&g_h1b[pix2]) = make_uint2(r0, r1);
}

// ---------------------------------------------------------------------------
// K2: conv2 (3x3 pad 1, 32->32) on bitplanes. One thread = 2 pixels.
// Weights + integer thresholds staged in smem (strided load: 288 > blockDim!).
// padding pads the *binarized* tensor with zeros -> border taps contribute 0.
// 131072 threads.
// ---------------------------------------------------------------------------
__global__ void __launch_bounds__(256) k_conv2()
{
    __shared__ uint32_t sw[CI * 9];
    __shared__ int stp[CI];
    __shared__ int str[CI];
    int tid = threadIdx.x;
    for (int i = tid; i < CI * 9; i += 256)        // 288 words: MUST stride
        sw[i] = ((const uint32_t*)g_wb2)[i];
    if (tid < CI) { stp[tid] = g_t2pi[tid]; str[tid] = g_t2ri[tid]; }
    __syncthreads();

    int t = blockIdx.x * 256 + tid;
    int pix2 = t << 1;
    int b  = pix2 >> 15;
    int hw = pix2 & (HW - 1);
    int h  = hw >> 8;          // Ww = 256
    int w0 = hw & (Ww - 1);    // even
    const uint32_t* hb = g_h1b + b * HW;
    uint32_t r0 = 0u, r1 = 0u;

    bool fast = (h > 0) & (h < Hh - 1) & (w0 > 0) & (w0 < Ww - 2);
    if (fast) {
        uint32_t n0[4], n1[4], n2[4];
        {
            int base = (h - 1) * Ww + w0;
            uint2 m = *reinterpret_cast<const uint2*>(hb + base);
            n0[0] = hb[base - 1]; n0[1] = m.x; n0[2] = m.y; n0[3] = hb[base + 2];
            base += Ww;
            m = *reinterpret_cast<const uint2*>(hb + base);
            n1[0] = hb[base - 1]; n1[1] = m.x; n1[2] = m.y; n1[3] = hb[base + 2];
            base += Ww;
            m = *reinterpret_cast<const uint2*>(hb + base);
            n2[0] = hb[base - 1]; n2[1] = m.x; n2[2] = m.y; n2[3] = hb[base + 2];
        }
        #pragma unroll 4
        for (int oc = 0; oc < CI; ++oc) {
            uint32_t wt0 = sw[oc*9+0], wt1 = sw[oc*9+1], wt2 = sw[oc*9+2];
            uint32_t wt3 = sw[oc*9+3], wt4 = sw[oc*9+4], wt5 = sw[oc*9+5];
            uint32_t wt6 = sw[oc*9+6], wt7 = sw[oc*9+7], wt8 = sw[oc*9+8];
            int th = stp[oc];
            int P0 = __popc(n0[0] ^ wt0) + __popc(n0[1] ^ wt1) + __popc(n0[2] ^ wt2)
                   + __popc(n1[0] ^ wt3) + __popc(n1[1] ^ wt4) + __popc(n1[2] ^ wt5)
                   + __popc(n2[0] ^ wt6) + __popc(n2[1] ^ wt7) + __popc(n2[2] ^ wt8);
            int P1 = __popc(n0[1] ^ wt0) + __popc(n0[2] ^ wt1) + __popc(n0[3] ^ wt2)
                   + __popc(n1[1] ^ wt3) + __popc(n1[2] ^ wt4) + __popc(n1[3] ^ wt5)
                   + __popc(n2[1] ^ wt6) + __popc(n2[2] ^ wt7) + __popc(n2[3] ^ wt8);
            if (P0 < th) r0 |= 1u << oc;
            if (P1 < th) r1 |= 1u << oc;
        }
    } else {
        uint32_t rr[2] = {0u, 0u};
        #pragma unroll
        for (int j = 0; j < 2; ++j) {
            int wj = w0 + j;
            uint32_t rb = 0u;
            for (int oc = 0; oc < CI; ++oc) {
                int acc = 0;
                for (int kh = 0; kh < 3; ++kh) {
                    int row = h - 1 + kh;
                    if (row < 0 || row >= Hh) continue;
                    for (int kw = 0; kw < 3; ++kw) {
                        int cc = wj - 1 + kw;
                        if (cc < 0 || cc >= Ww) continue;
                        acc += 32 - 2 * __popc(hb[row * Ww + cc] ^ sw[oc * 9 + kh * 3 + kw]);
                    }
                }
                if (acc > str[oc]) rb |= 1u << oc;
            }
            rr[j] = rb;
        }
        r0 = rr[0]; r1 = rr[1];
    }
    *reinterpret_cast<uint2*>(&g_h2b[pix2]) = make_uint2(r0, r1);
}

// ---------------------------------------------------------------------------
// K3: conv3 (1x1, 32->128) + bn3 + prelu3 + residual + prelu_out.
// One thread = 8 consecutive outputs (2x float4 in/out, streaming x/out).
// 4194304 threads.
// ---------------------------------------------------------------------------
__device__ __forceinline__ float conv3_elem(uint32_t hbits, uint32_t wv,
                                            float fa, float fb, float xv,
                                            float a3, float aout)
{
    float f = fmaf((float)__popc(hbits ^ wv), fa, fb);
    f = fmaxf(f, 0.f) + a3 * fminf(f, 0.f);
    float s = f + xv;
    return fmaxf(s, 0.f) + aout * fminf(s, 0.f);
}

__global__ void __launch_bounds__(256) k_conv3(const float* __restrict__ x,
                                               float* __restrict__ out,
                                               const float* __restrict__ a3p,
                                               const float* __restrict__ aoutp)
{
    int t = blockIdx.x * 256 + threadIdx.x;     // 0 .. 4194303
    int b   = t >> 19;                           // Cc * (HW/8) = 2^19
    int oc  = (t >> 12) & (Cc - 1);              // HW/8 = 4096
    int hw8 = t & 4095;

    float a3   = __ldg(a3p);
    float aout = __ldg(aoutp);
    float fa = g_fa3[oc], fb = g_fb3[oc];
    uint32_t wv = g_wb3[oc];

    const uint4* hp = reinterpret_cast<const uint4*>(&g_h2b[(b << 15) + (hw8 << 3)]);
    uint4 h0 = hp[0], h1 = hp[1];

    size_t i8 = (size_t)t << 3;
    float4 xv0 = __ldcs(reinterpret_cast<const float4*>(x + i8));
    float4 xv1 = __ldcs(reinterpret_cast<const float4*>(x + i8 + 4));

    float4 o0, o1;
    o0.x = conv3_elem(h0.x, wv, fa, fb, xv0.x, a3, aout);
    o0.y = conv3_elem(h0.y, wv, fa, fb, xv0.y, a3, aout);
    o0.z = conv3_elem(h0.z, wv, fa, fb, xv0.z, a3, aout);
    o0.w = conv3_elem(h0.w, wv, fa, fb, xv0.w, a3, aout);
    o1.x = conv3_elem(h1.x, wv, fa, fb, xv1.x, a3, aout);
    o1.y = conv3_elem(h1.y, wv, fa, fb, xv1.y, a3, aout);
    o1.z = conv3_elem(h1.z, wv, fa, fb, xv1.z, a3, aout);
    o1.w = conv3_elem(h1.w, wv, fa, fb, xv1.w, a3, aout);

    __stcs(reinterpret_cast<float4*>(out + i8), o0);
    __stcs(reinterpret_cast<float4*>(out + i8 + 4), o1);
}

// ---------------------------------------------------------------------------
extern "C" void kernel_launch(void* const* d_in, const int* in_sizes, int n_in,
                              void* d_out, int out_size)
{
    (void)in_sizes; (void)n_in; (void)out_size;
    const float* x  = (const float*)d_in[0];
    const float* w1 = (const float*)d_in[1];
    const float* g1 = (const float*)d_in[2];
    const float* b1 = (const float*)d_in[3];
    const float* m1 = (const float*)d_in[4];
    const float* v1 = (const float*)d_in[5];
    /* a1 = d_in[6] (unused: sign-preserving) */
    const float* w2 = (const float*)d_in[7];
    const float* g2 = (const float*)d_in[8];
    const float* b2 = (const float*)d_in[9];
    const float* m2 = (const float*)d_in[10];
    const float* v2 = (const float*)d_in[11];
    /* a2 = d_in[12] (unused) */
    const float* w3 = (const float*)d_in[13];
    const float* g3 = (const float*)d_in[14];
    const float* b3 = (const float*)d_in[15];
    const float* m3 = (const float*)d_in[16];
    const float* v3 = (const float*)d_in[17];
    const float* a3   = (const float*)d_in[18];
    const float* aout = (const float*)d_in[19];

    k_prep<<<1, 512>>>(w1, g1, b1, m1, v1,
                       w2, g2, b2, m2, v2,
                       w3, g3, b3, m3, v3);
    k_conv1<<<512, 256>>>(x);
    k_conv2<<<512, 256>>>();
    k_conv3<<<16384, 256>>>(x, (float*)d_out, a3, aout);
}